// round 6
// baseline (speedup 1.0000x reference)
#include <cuda_runtime.h>
#include <cuda_bf16.h>
#include <cstdint>

// Problem constants (fixed by the reference)
#define NN    100000      // nodes
#define DIN   512
#define DOUT  512
#define EMAX  3200000     // edges

// Scratch (device globals per harness alloc rules)
__device__ float g_support[(size_t)NN * DOUT];     // 200 MB
__device__ int   g_counts [NN];
__device__ int   g_offsets[NN + 1];
__device__ int   g_cursor [NN];
__device__ int   g_blocksums[128];
__device__ int   g_ecol[EMAX];
__device__ float g_eval[EMAX];
__device__ int   g_idx_is64;

#define SCAN_ELEMS 1024
#define SCAN_NB   ((NN + SCAN_ELEMS - 1) / SCAN_ELEMS)   // 98

// ---------------------------------------------------------------------------
// Kernel: detect index dtype (int64 vs int32-packed).
// ---------------------------------------------------------------------------
__global__ void detect_idx_kernel(const long long* __restrict__ rows, int n_edges)
{
    __shared__ int bad;
    if (threadIdx.x == 0) bad = 0;
    __syncthreads();
    int limit = 2048;
    if (limit > n_edges / 2) limit = n_edges / 2;
    for (int i = threadIdx.x; i < limit; i += blockDim.x) {
        long long v = rows[i];
        if (v < 0 || v >= NN) bad = 1;
    }
    __syncthreads();
    if (threadIdx.x == 0) g_idx_is64 = bad ? 0 : 1;
}

__device__ __forceinline__ long long load_idx(const void* p, int e)
{
    if (g_idx_is64) return ((const long long*)p)[e];
    return (long long)((const int*)p)[e];
}

// ---------------------------------------------------------------------------
// CSR build, phase 1: histogram of destination rows. 128-thr blocks so they
// can slot into RF/warp-slot gaps while the GEMM occupies the SMs.
// ---------------------------------------------------------------------------
__global__ __launch_bounds__(128)
void hist_kernel(const void* __restrict__ rows, int E)
{
    int stride = gridDim.x * blockDim.x;
    for (int e = blockIdx.x * blockDim.x + threadIdx.x; e < E; e += stride) {
        int r = (int)load_idx(rows, e);
        atomicAdd(&g_counts[r], 1);
    }
}

// ---------------------------------------------------------------------------
// CSR build, phase 2a: per-scan-block sums (1024 counts each).
// ---------------------------------------------------------------------------
__global__ __launch_bounds__(256)
void scan_blocksum_kernel()
{
    __shared__ int sh[256];
    int b = blockIdx.x, t = threadIdx.x;
    int base = b * SCAN_ELEMS + t * 4;
    int s = 0;
#pragma unroll
    for (int i = 0; i < 4; i++) {
        int idx = base + i;
        if (idx < NN) s += g_counts[idx];
    }
    sh[t] = s; __syncthreads();
    for (int off = 128; off > 0; off >>= 1) {
        if (t < off) sh[t] += sh[t + off];
        __syncthreads();
    }
    if (t == 0) g_blocksums[b] = sh[0];
}

// ---------------------------------------------------------------------------
// CSR build, phase 2b: exclusive scan of the 98 block sums (1 block, serial).
// ---------------------------------------------------------------------------
__global__ void scan_top_kernel(int E)
{
    if (threadIdx.x == 0) {
        int run = 0;
        for (int i = 0; i < SCAN_NB; i++) {
            int v = g_blocksums[i];
            g_blocksums[i] = run;
            run += v;
        }
        g_offsets[NN] = E;
    }
}

// ---------------------------------------------------------------------------
// CSR build, phase 2c: per-block exclusive scan -> offsets, cursor.
// ---------------------------------------------------------------------------
__global__ __launch_bounds__(256)
void scan_write_kernel()
{
    __shared__ int sh[256];
    int b = blockIdx.x, t = threadIdx.x;
    int base = b * SCAN_ELEMS + t * 4;
    int v[4];
#pragma unroll
    for (int i = 0; i < 4; i++)
        v[i] = (base + i < NN) ? g_counts[base + i] : 0;
    int s = v[0] + v[1] + v[2] + v[3];
    sh[t] = s; __syncthreads();
    for (int off = 1; off < 256; off <<= 1) {
        int x = (t >= off) ? sh[t - off] : 0;
        __syncthreads();
        sh[t] += x;
        __syncthreads();
    }
    int excl = sh[t] - s + g_blocksums[b];
#pragma unroll
    for (int i = 0; i < 4; i++) {
        int idx = base + i;
        if (idx < NN) {
            g_offsets[idx] = excl;
            g_cursor[idx]  = excl;
        }
        excl += v[i];
    }
}

// ---------------------------------------------------------------------------
// CSR build, phase 3: permute (col, val) pairs into CSR slots. 128-thr blocks.
// ---------------------------------------------------------------------------
__global__ __launch_bounds__(128)
void bucket_kernel(const void* __restrict__ rows, const void* __restrict__ cols,
                   const float* __restrict__ vals, int E)
{
    int stride = gridDim.x * blockDim.x;
    for (int e = blockIdx.x * blockDim.x + threadIdx.x; e < E; e += stride) {
        int r = (int)load_idx(rows, e);
        int c = (int)load_idx(cols, e);
        int pos = atomicAdd(&g_cursor[r], 1);
        g_ecol[pos] = c;
        g_eval[pos] = vals[e];
    }
}

// ---------------------------------------------------------------------------
// Aggregation: one block (128 thr) per node, register accumulation, fused ReLU.
// ---------------------------------------------------------------------------
__global__ __launch_bounds__(128)
void aggregate_kernel(const float* __restrict__ sup, float* __restrict__ out)
{
    const int node = blockIdx.x;
    const int t = threadIdx.x;
    const int beg = g_offsets[node];
    const int end = g_offsets[node + 1];

    __shared__ int   sc[128];
    __shared__ float sv[128];

    float4 acc = make_float4(0.f, 0.f, 0.f, 0.f);

    for (int j0 = beg; j0 < end; j0 += 128) {
        int m = end - j0; if (m > 128) m = 128;
        if (t < m) { sc[t] = g_ecol[j0 + t]; sv[t] = g_eval[j0 + t]; }
        __syncthreads();

        int k = 0;
        for (; k + 4 <= m; k += 4) {
            const float4* p0 = (const float4*)(sup + (long long)sc[k + 0] * DOUT) + t;
            const float4* p1 = (const float4*)(sup + (long long)sc[k + 1] * DOUT) + t;
            const float4* p2 = (const float4*)(sup + (long long)sc[k + 2] * DOUT) + t;
            const float4* p3 = (const float4*)(sup + (long long)sc[k + 3] * DOUT) + t;
            float4 s0 = __ldg(p0), s1 = __ldg(p1), s2 = __ldg(p2), s3 = __ldg(p3);
            float v0 = sv[k + 0], v1 = sv[k + 1], v2 = sv[k + 2], v3 = sv[k + 3];
            acc.x += v0 * s0.x; acc.y += v0 * s0.y; acc.z += v0 * s0.z; acc.w += v0 * s0.w;
            acc.x += v1 * s1.x; acc.y += v1 * s1.y; acc.z += v1 * s1.z; acc.w += v1 * s1.w;
            acc.x += v2 * s2.x; acc.y += v2 * s2.y; acc.z += v2 * s2.z; acc.w += v2 * s2.w;
            acc.x += v3 * s3.x; acc.y += v3 * s3.y; acc.z += v3 * s3.z; acc.w += v3 * s3.w;
        }
        for (; k < m; k++) {
            float4 s = __ldg((const float4*)(sup + (long long)sc[k] * DOUT) + t);
            float v = sv[k];
            acc.x += v * s.x; acc.y += v * s.y; acc.z += v * s.z; acc.w += v * s.w;
        }
        __syncthreads();
    }

    acc.x = fmaxf(acc.x, 0.f); acc.y = fmaxf(acc.y, 0.f);
    acc.z = fmaxf(acc.z, 0.f); acc.w = fmaxf(acc.w, 0.f);
    ((float4*)out)[(long long)node * (DOUT / 4) + t] = acc;
}

// ---------------------------------------------------------------------------
// TF32 tensor-core GEMM (legacy mma.sync; proven R2/R4 kernel, ~500us)
// ---------------------------------------------------------------------------
#define AS_STRIDE 36
#define BS_STRIDE 132
#define A_BUF_WORDS (128 * AS_STRIDE)
#define B_BUF_WORDS (32 * BS_STRIDE)
#define SMEM_WORDS  (2 * A_BUF_WORDS + 2 * B_BUF_WORDS)

__device__ __forceinline__ void cp_async16(uint32_t saddr, const void* gptr, int src_bytes)
{
    asm volatile("cp.async.cg.shared.global [%0], [%1], 16, %2;\n"
                 :: "r"(saddr), "l"(gptr), "r"(src_bytes));
}

__global__ __launch_bounds__(256, 2)
void gemm_tf32_kernel(const float* __restrict__ A, const float* __restrict__ B,
                      float* __restrict__ C, int M)
{
    extern __shared__ uint32_t smem[];
    const int tid  = threadIdx.x;
    const int wid  = tid >> 5;
    const int lane = tid & 31;
    const int gid  = lane >> 2;
    const int tg   = lane & 3;

    const int blockRow = blockIdx.y * 128;
    const int blockCol = blockIdx.x * 128;

    const int aRowL = tid >> 3;
    const int aColL = (tid & 7) * 4;
    const int bRowL = tid >> 5;
    const int bColL = (tid & 31) * 4;

    uint32_t smem_base;
    asm("{ .reg .u64 t; cvta.to.shared.u64 t, %1; cvt.u32.u64 %0, t; }"
        : "=r"(smem_base) : "l"(smem));

    const int warpM = (wid & 1) * 64;
    const int warpN = (wid >> 1) * 32;

    float acc[4][4][4];
#pragma unroll
    for (int i = 0; i < 4; i++)
#pragma unroll
        for (int j = 0; j < 4; j++)
#pragma unroll
            for (int t = 0; t < 4; t++) acc[i][j][t] = 0.f;

    auto issue_chunk = [&](int chunk, int buf) {
#pragma unroll
        for (int i = 0; i < 4; i++) {
            int r = aRowL + 32 * i;
            long long gRow = (long long)blockRow + r;
            bool ok = gRow < M;
            const float* src = A + (ok ? gRow : 0) * DIN + chunk * 32 + aColL;
            uint32_t dst = smem_base + (buf * A_BUF_WORDS + r * AS_STRIDE + aColL) * 4;
            cp_async16(dst, src, ok ? 16 : 0);
        }
#pragma unroll
        for (int i = 0; i < 4; i++) {
            int kr = bRowL + 8 * i;
            const float* src = B + (long long)(chunk * 32 + kr) * DOUT + blockCol + bColL;
            uint32_t dst = smem_base +
                (2 * A_BUF_WORDS + buf * B_BUF_WORDS + kr * BS_STRIDE + bColL) * 4;
            cp_async16(dst, src, 16);
        }
        asm volatile("cp.async.commit_group;");
    };

    issue_chunk(0, 0);

    const int NCHUNK = DIN / 32;
    int buf = 0;
    for (int c = 0; c < NCHUNK; c++) {
        if (c + 1 < NCHUNK) {
            issue_chunk(c + 1, buf ^ 1);
            asm volatile("cp.async.wait_group 1;");
        } else {
            asm volatile("cp.async.wait_group 0;");
        }
        __syncthreads();

        const uint32_t* As = smem + buf * A_BUF_WORDS;
        const uint32_t* Bs = smem + 2 * A_BUF_WORDS + buf * B_BUF_WORDS;

#pragma unroll
        for (int ks = 0; ks < 4; ks++) {
            const int kk = ks * 8;
            uint32_t afr[4][4], bfr[4][2];
#pragma unroll
            for (int i = 0; i < 4; i++) {
                int r0 = warpM + i * 16 + gid;
                afr[i][0] = As[(r0)     * AS_STRIDE + kk + tg];
                afr[i][1] = As[(r0 + 8) * AS_STRIDE + kk + tg];
                afr[i][2] = As[(r0)     * AS_STRIDE + kk + tg + 4];
                afr[i][3] = As[(r0 + 8) * AS_STRIDE + kk + tg + 4];
            }
#pragma unroll
            for (int j = 0; j < 4; j++) {
                int cn = warpN + j * 8 + gid;
                bfr[j][0] = Bs[(kk + tg)     * BS_STRIDE + cn];
                bfr[j][1] = Bs[(kk + tg + 4) * BS_STRIDE + cn];
            }
#pragma unroll
            for (int i = 0; i < 4; i++)
#pragma unroll
                for (int j = 0; j < 4; j++) {
                    asm volatile(
                        "mma.sync.aligned.m16n8k8.row.col.f32.tf32.tf32.f32 "
                        "{%0,%1,%2,%3}, {%4,%5,%6,%7}, {%8,%9}, {%0,%1,%2,%3};"
                        : "+f"(acc[i][j][0]), "+f"(acc[i][j][1]),
                          "+f"(acc[i][j][2]), "+f"(acc[i][j][3])
                        : "r"(afr[i][0]), "r"(afr[i][1]), "r"(afr[i][2]), "r"(afr[i][3]),
                          "r"(bfr[j][0]), "r"(bfr[j][1]));
                }
        }
        __syncthreads();
        buf ^= 1;
    }

#pragma unroll
    for (int i = 0; i < 4; i++) {
        long long row0 = (long long)blockRow + warpM + i * 16 + gid;
#pragma unroll
        for (int j = 0; j < 4; j++) {
            int col = blockCol + warpN + j * 8 + tg * 2;
            if (row0 < M)
                *(float2*)(C + row0 * DOUT + col) = make_float2(acc[i][j][0], acc[i][j][1]);
            if (row0 + 8 < M)
                *(float2*)(C + (row0 + 8) * DOUT + col) = make_float2(acc[i][j][2], acc[i][j][3]);
        }
    }
}

// ---------------------------------------------------------------------------
// kernel_launch: fork/join, CSR branch on a HIGH-PRIORITY side stream so the
// work distributor interleaves its CTAs with the 3128-CTA GEMM grid.
// ---------------------------------------------------------------------------
extern "C" void kernel_launch(void* const* d_in, const int* in_sizes, int n_in,
                              void* d_out, int out_size)
{
    const float* features = (const float*)d_in[0];
    const float* weight   = (const float*)d_in[1];
    const void*  rows     = d_in[2];
    const void*  cols     = d_in[3];
    const float* vals     = (const float*)d_in[4];
    float* out = (float*)d_out;

    const int M = in_sizes[0] / DIN;   // 100000
    const int E = in_sizes[4];         // 3200000

    float* sup = nullptr;
    cudaGetSymbolAddress((void**)&sup, g_support);
    int* counts_ptr = nullptr;
    cudaGetSymbolAddress((void**)&counts_ptr, g_counts);

    static bool init_done = false;
    static cudaStream_t s1;
    static cudaEvent_t ev_fork, ev_join;
    if (!init_done) {
        cudaFuncSetAttribute(gemm_tf32_kernel,
                             cudaFuncAttributeMaxDynamicSharedMemorySize,
                             SMEM_WORDS * 4);
        int prio_lo = 0, prio_hi = 0;
        cudaDeviceGetStreamPriorityRange(&prio_lo, &prio_hi);   // hi = most negative
        cudaStreamCreateWithPriority(&s1, cudaStreamNonBlocking, prio_hi);
        cudaEventCreateWithFlags(&ev_fork, cudaEventDisableTiming);
        cudaEventCreateWithFlags(&ev_join, cudaEventDisableTiming);
        init_done = true;
    }

    // ---- fork ----
    cudaEventRecord(ev_fork, 0);
    cudaStreamWaitEvent(s1, ev_fork, 0);

    // Branch B (high-priority side stream): CSR build
    cudaMemsetAsync(counts_ptr, 0, (size_t)NN * sizeof(int), s1);
    detect_idx_kernel<<<1, 256, 0, s1>>>((const long long*)rows, E);
    hist_kernel<<<4096, 128, 0, s1>>>(rows, E);
    scan_blocksum_kernel<<<SCAN_NB, 256, 0, s1>>>();
    scan_top_kernel<<<1, 32, 0, s1>>>(E);
    scan_write_kernel<<<SCAN_NB, 256, 0, s1>>>();
    bucket_kernel<<<4096, 128, 0, s1>>>(rows, cols, vals, E);
    cudaEventRecord(ev_join, s1);

    // Branch A (capture stream): dense projection on tensor cores (tf32)
    dim3 gemm_grid(DOUT / 128, (M + 127) / 128);
    gemm_tf32_kernel<<<gemm_grid, 256, SMEM_WORDS * 4>>>(features, weight, sup, M);

    // ---- join ----
    cudaStreamWaitEvent(0, ev_join, 0);

    // Aggregation + fused ReLU
    aggregate_kernel<<<M, 128>>>(sup, out);
}

// round 7
// speedup vs baseline: 1.1318x; 1.1318x over previous
#include <cuda_runtime.h>
#include <cuda_fp16.h>
#include <cstdint>

// Problem constants (fixed by the reference)
#define NN    100000      // nodes
#define DIN   512
#define DOUT  512
#define EMAX  3200000     // edges

// Scratch (device globals per harness alloc rules)
__device__ float  g_support[(size_t)NN * DOUT];    // 200 MB
__device__ __half g_Ah[(size_t)NN * DIN];          // 100 MB, A in fp16
__device__ __half g_Bth[DIN * DOUT];               // 0.5 MB, W^T in fp16 (n-major)
__device__ int    g_counts [NN];
__device__ int    g_offsets[NN + 1];
__device__ int    g_cursor [NN];
__device__ int    g_blocksums[128];
__device__ int    g_ecol[EMAX];
__device__ float  g_eval[EMAX];
__device__ int    g_idx_is64;

#define SCAN_ELEMS 1024
#define SCAN_NB   ((NN + SCAN_ELEMS - 1) / SCAN_ELEMS)   // 98

// ---------------------------------------------------------------------------
// Kernel: detect index dtype (int64 vs int32-packed).
// ---------------------------------------------------------------------------
__global__ void detect_idx_kernel(const long long* __restrict__ rows, int n_edges)
{
    __shared__ int bad;
    if (threadIdx.x == 0) bad = 0;
    __syncthreads();
    int limit = 2048;
    if (limit > n_edges / 2) limit = n_edges / 2;
    for (int i = threadIdx.x; i < limit; i += blockDim.x) {
        long long v = rows[i];
        if (v < 0 || v >= NN) bad = 1;
    }
    __syncthreads();
    if (threadIdx.x == 0) g_idx_is64 = bad ? 0 : 1;
}

__device__ __forceinline__ long long load_idx(const void* p, int e)
{
    if (g_idx_is64) return ((const long long*)p)[e];
    return (long long)((const int*)p)[e];
}

// ---------------------------------------------------------------------------
// Convert A fp32 -> fp16 (streaming, float4 in / half2 out).
// ---------------------------------------------------------------------------
__global__ __launch_bounds__(256)
void convert_a_kernel(const float4* __restrict__ in, __half2* __restrict__ out,
                      long long n4)
{
    long long i = (long long)blockIdx.x * blockDim.x + threadIdx.x;
    long long stride = (long long)gridDim.x * blockDim.x;
    for (; i < n4; i += stride) {
        float4 v = in[i];
        out[i * 2 + 0] = __floats2half2_rn(v.x, v.y);
        out[i * 2 + 1] = __floats2half2_rn(v.z, v.w);
    }
}

// ---------------------------------------------------------------------------
// Convert + transpose W: Bth[n][k] = (half)W[k][n].
// ---------------------------------------------------------------------------
__global__ void convert_w_kernel(const float* __restrict__ W, __half* __restrict__ Bth)
{
    __shared__ float tile[32][33];
    int bx = blockIdx.x * 32, by = blockIdx.y * 32;   // bx: n, by: k
    int tx = threadIdx.x, ty = threadIdx.y;           // 32 x 8
#pragma unroll
    for (int i = 0; i < 32; i += 8)
        tile[ty + i][tx] = W[(by + ty + i) * DOUT + bx + tx];
    __syncthreads();
#pragma unroll
    for (int i = 0; i < 32; i += 8)
        Bth[(long long)(bx + ty + i) * DIN + by + tx] = __float2half_rn(tile[tx][ty + i]);
}

// ---------------------------------------------------------------------------
// FP16 tensor-core GEMM  C[M,512] = Ah[M,512] * Bth[512,512]^T, fp32 accum.
// BM=BN=128, BK=64, 8 warps (2Mx4N), warp tile 64x32.
// mma.sync.aligned.m16n8k16.row.col.f32.f16.f16.f32 — K=16/instr (2x tf32).
// Words = 2 packed fp16. cp.async double-buffered.
// ---------------------------------------------------------------------------
#define HS_STRIDE 36                        // uint32 words per tile row (+pad)
#define H_BUF_WORDS (128 * HS_STRIDE)       // 4608 words per operand buffer
#define H_SMEM_WORDS (4 * H_BUF_WORDS)      // 18432 words = 73728 B

__device__ __forceinline__ void cp_async16(uint32_t saddr, const void* gptr, int src_bytes)
{
    asm volatile("cp.async.cg.shared.global [%0], [%1], 16, %2;\n"
                 :: "r"(saddr), "l"(gptr), "r"(src_bytes));
}

__global__ __launch_bounds__(256, 2)
void gemm_fp16_kernel(const __half* __restrict__ A, const __half* __restrict__ Bt,
                      float* __restrict__ C, int M)
{
    extern __shared__ uint32_t smem[];
    const int tid  = threadIdx.x;
    const int wid  = tid >> 5;
    const int lane = tid & 31;
    const int gid  = lane >> 2;   // 0..7
    const int tg   = lane & 3;    // 0..3

    const int blockRow = blockIdx.y * 128;
    const int blockCol = blockIdx.x * 128;

    // loader mapping: 4 cp.async16 per thread per operand per chunk
    // rows (tid>>3) + 32*l, word col (tid&7)*4  (4 words = 8 fp16 = 16 B)
    const int ldRow = tid >> 3;           // 0..31
    const int ldCol = (tid & 7) * 4;      // word col

    uint32_t smem_base;
    asm("{ .reg .u64 t; cvta.to.shared.u64 t, %1; cvt.u32.u64 %0, t; }"
        : "=r"(smem_base) : "l"(smem));

    const int warpM = (wid & 1) * 64;
    const int warpN = (wid >> 1) * 32;

    float acc[4][4][4];
#pragma unroll
    for (int i = 0; i < 4; i++)
#pragma unroll
        for (int j = 0; j < 4; j++)
#pragma unroll
            for (int t = 0; t < 4; t++) acc[i][j][t] = 0.f;

    auto issue_chunk = [&](int chunk, int buf) {
        const int kElem = chunk * 64 + ldCol * 2;   // fp16 element offset in k
#pragma unroll
        for (int l = 0; l < 4; l++) {
            int r = ldRow + 32 * l;
            long long gRow = (long long)blockRow + r;
            bool ok = gRow < M;
            const __half* src = A + (ok ? gRow : 0) * DIN + kElem;
            uint32_t dst = smem_base + (buf * H_BUF_WORDS + r * HS_STRIDE + ldCol) * 4;
            cp_async16(dst, src, ok ? 16 : 0);
        }
#pragma unroll
        for (int l = 0; l < 4; l++) {
            int n = ldRow + 32 * l;
            const __half* src = Bt + (long long)(blockCol + n) * DIN + kElem;
            uint32_t dst = smem_base +
                ((2 + buf) * H_BUF_WORDS + n * HS_STRIDE + ldCol) * 4;
            cp_async16(dst, src, 16);
        }
        asm volatile("cp.async.commit_group;");
    };

    issue_chunk(0, 0);

    const int NCHUNK = DIN / 64;   // 8
    int buf = 0;
    for (int c = 0; c < NCHUNK; c++) {
        if (c + 1 < NCHUNK) {
            issue_chunk(c + 1, buf ^ 1);
            asm volatile("cp.async.wait_group 1;");
        } else {
            asm volatile("cp.async.wait_group 0;");
        }
        __syncthreads();

        const uint32_t* As = smem + buf * H_BUF_WORDS;
        const uint32_t* Bs = smem + (2 + buf) * H_BUF_WORDS;

#pragma unroll
        for (int s = 0; s < 4; s++) {          // 4 k-steps of 16 (words: 8/step)
            const int kw = s * 8;
            uint32_t afr[4][4], bfr[4][2];
#pragma unroll
            for (int i = 0; i < 4; i++) {
                int r0 = warpM + i * 16 + gid;
                afr[i][0] = As[(r0)     * HS_STRIDE + kw + tg];       // rows 0-7,  k 0-7
                afr[i][1] = As[(r0 + 8) * HS_STRIDE + kw + tg];       // rows 8-15, k 0-7
                afr[i][2] = As[(r0)     * HS_STRIDE + kw + 4 + tg];   // rows 0-7,  k 8-15
                afr[i][3] = As[(r0 + 8) * HS_STRIDE + kw + 4 + tg];   // rows 8-15, k 8-15
            }
#pragma unroll
            for (int j = 0; j < 4; j++) {
                int nn = warpN + j * 8 + gid;
                bfr[j][0] = Bs[nn * HS_STRIDE + kw + tg];             // k 0-7
                bfr[j][1] = Bs[nn * HS_STRIDE + kw + 4 + tg];         // k 8-15
            }
#pragma unroll
            for (int i = 0; i < 4; i++)
#pragma unroll
                for (int j = 0; j < 4; j++) {
                    asm volatile(
                        "mma.sync.aligned.m16n8k16.row.col.f32.f16.f16.f32 "
                        "{%0,%1,%2,%3}, {%4,%5,%6,%7}, {%8,%9}, {%0,%1,%2,%3};"
                        : "+f"(acc[i][j][0]), "+f"(acc[i][j][1]),
                          "+f"(acc[i][j][2]), "+f"(acc[i][j][3])
                        : "r"(afr[i][0]), "r"(afr[i][1]), "r"(afr[i][2]), "r"(afr[i][3]),
                          "r"(bfr[j][0]), "r"(bfr[j][1]));
                }
        }
        __syncthreads();
        buf ^= 1;
    }

#pragma unroll
    for (int i = 0; i < 4; i++) {
        long long row0 = (long long)blockRow + warpM + i * 16 + gid;
#pragma unroll
        for (int j = 0; j < 4; j++) {
            int col = blockCol + warpN + j * 8 + tg * 2;
            if (row0 < M)
                *(float2*)(C + row0 * DOUT + col) = make_float2(acc[i][j][0], acc[i][j][1]);
            if (row0 + 8 < M)
                *(float2*)(C + (row0 + 8) * DOUT + col) = make_float2(acc[i][j][2], acc[i][j][3]);
        }
    }
}

// ---------------------------------------------------------------------------
// CSR build (unchanged R4/R6)
// ---------------------------------------------------------------------------
__global__ __launch_bounds__(128)
void hist_kernel(const void* __restrict__ rows, int E)
{
    int stride = gridDim.x * blockDim.x;
    for (int e = blockIdx.x * blockDim.x + threadIdx.x; e < E; e += stride) {
        int r = (int)load_idx(rows, e);
        atomicAdd(&g_counts[r], 1);
    }
}

__global__ __launch_bounds__(256)
void scan_blocksum_kernel()
{
    __shared__ int sh[256];
    int b = blockIdx.x, t = threadIdx.x;
    int base = b * SCAN_ELEMS + t * 4;
    int s = 0;
#pragma unroll
    for (int i = 0; i < 4; i++) {
        int idx = base + i;
        if (idx < NN) s += g_counts[idx];
    }
    sh[t] = s; __syncthreads();
    for (int off = 128; off > 0; off >>= 1) {
        if (t < off) sh[t] += sh[t + off];
        __syncthreads();
    }
    if (t == 0) g_blocksums[b] = sh[0];
}

__global__ void scan_top_kernel(int E)
{
    if (threadIdx.x == 0) {
        int run = 0;
        for (int i = 0; i < SCAN_NB; i++) {
            int v = g_blocksums[i];
            g_blocksums[i] = run;
            run += v;
        }
        g_offsets[NN] = E;
    }
}

__global__ __launch_bounds__(256)
void scan_write_kernel()
{
    __shared__ int sh[256];
    int b = blockIdx.x, t = threadIdx.x;
    int base = b * SCAN_ELEMS + t * 4;
    int v[4];
#pragma unroll
    for (int i = 0; i < 4; i++)
        v[i] = (base + i < NN) ? g_counts[base + i] : 0;
    int s = v[0] + v[1] + v[2] + v[3];
    sh[t] = s; __syncthreads();
    for (int off = 1; off < 256; off <<= 1) {
        int x = (t >= off) ? sh[t - off] : 0;
        __syncthreads();
        sh[t] += x;
        __syncthreads();
    }
    int excl = sh[t] - s + g_blocksums[b];
#pragma unroll
    for (int i = 0; i < 4; i++) {
        int idx = base + i;
        if (idx < NN) {
            g_offsets[idx] = excl;
            g_cursor[idx]  = excl;
        }
        excl += v[i];
    }
}

__global__ __launch_bounds__(128)
void bucket_kernel(const void* __restrict__ rows, const void* __restrict__ cols,
                   const float* __restrict__ vals, int E)
{
    int stride = gridDim.x * blockDim.x;
    for (int e = blockIdx.x * blockDim.x + threadIdx.x; e < E; e += stride) {
        int r = (int)load_idx(rows, e);
        int c = (int)load_idx(cols, e);
        int pos = atomicAdd(&g_cursor[r], 1);
        g_ecol[pos] = c;
        g_eval[pos] = vals[e];
    }
}

// ---------------------------------------------------------------------------
// Aggregation: one block (128 thr) per node, register accumulation, fused ReLU.
// ---------------------------------------------------------------------------
__global__ __launch_bounds__(128)
void aggregate_kernel(const float* __restrict__ sup, float* __restrict__ out)
{
    const int node = blockIdx.x;
    const int t = threadIdx.x;
    const int beg = g_offsets[node];
    const int end = g_offsets[node + 1];

    __shared__ int   sc[128];
    __shared__ float sv[128];

    float4 acc = make_float4(0.f, 0.f, 0.f, 0.f);

    for (int j0 = beg; j0 < end; j0 += 128) {
        int m = end - j0; if (m > 128) m = 128;
        if (t < m) { sc[t] = g_ecol[j0 + t]; sv[t] = g_eval[j0 + t]; }
        __syncthreads();

        int k = 0;
        for (; k + 4 <= m; k += 4) {
            const float4* p0 = (const float4*)(sup + (long long)sc[k + 0] * DOUT) + t;
            const float4* p1 = (const float4*)(sup + (long long)sc[k + 1] * DOUT) + t;
            const float4* p2 = (const float4*)(sup + (long long)sc[k + 2] * DOUT) + t;
            const float4* p3 = (const float4*)(sup + (long long)sc[k + 3] * DOUT) + t;
            float4 s0 = __ldg(p0), s1 = __ldg(p1), s2 = __ldg(p2), s3 = __ldg(p3);
            float v0 = sv[k + 0], v1 = sv[k + 1], v2 = sv[k + 2], v3 = sv[k + 3];
            acc.x += v0 * s0.x; acc.y += v0 * s0.y; acc.z += v0 * s0.z; acc.w += v0 * s0.w;
            acc.x += v1 * s1.x; acc.y += v1 * s1.y; acc.z += v1 * s1.z; acc.w += v1 * s1.w;
            acc.x += v2 * s2.x; acc.y += v2 * s2.y; acc.z += v2 * s2.z; acc.w += v2 * s2.w;
            acc.x += v3 * s3.x; acc.y += v3 * s3.y; acc.z += v3 * s3.z; acc.w += v3 * s3.w;
        }
        for (; k < m; k++) {
            float4 s = __ldg((const float4*)(sup + (long long)sc[k] * DOUT) + t);
            float v = sv[k];
            acc.x += v * s.x; acc.y += v * s.y; acc.z += v * s.z; acc.w += v * s.w;
        }
        __syncthreads();
    }

    acc.x = fmaxf(acc.x, 0.f); acc.y = fmaxf(acc.y, 0.f);
    acc.z = fmaxf(acc.z, 0.f); acc.w = fmaxf(acc.w, 0.f);
    ((float4*)out)[(long long)node * (DOUT / 4) + t] = acc;
}

// ---------------------------------------------------------------------------
// kernel_launch: s0 = convert A/W + fp16 GEMM; s1 = CSR build; join; aggregate
// ---------------------------------------------------------------------------
extern "C" void kernel_launch(void* const* d_in, const int* in_sizes, int n_in,
                              void* d_out, int out_size)
{
    const float* features = (const float*)d_in[0];
    const float* weight   = (const float*)d_in[1];
    const void*  rows     = d_in[2];
    const void*  cols     = d_in[3];
    const float* vals     = (const float*)d_in[4];
    float* out = (float*)d_out;

    const int M = in_sizes[0] / DIN;   // 100000
    const int E = in_sizes[4];         // 3200000

    float* sup = nullptr;
    cudaGetSymbolAddress((void**)&sup, g_support);
    __half* ah = nullptr;
    cudaGetSymbolAddress((void**)&ah, g_Ah);
    __half* bth = nullptr;
    cudaGetSymbolAddress((void**)&bth, g_Bth);
    int* counts_ptr = nullptr;
    cudaGetSymbolAddress((void**)&counts_ptr, g_counts);

    static bool init_done = false;
    static cudaStream_t s1;
    static cudaEvent_t ev_fork, ev_join;
    if (!init_done) {
        cudaFuncSetAttribute(gemm_fp16_kernel,
                             cudaFuncAttributeMaxDynamicSharedMemorySize,
                             H_SMEM_WORDS * 4);
        cudaStreamCreateWithFlags(&s1, cudaStreamNonBlocking);
        cudaEventCreateWithFlags(&ev_fork, cudaEventDisableTiming);
        cudaEventCreateWithFlags(&ev_join, cudaEventDisableTiming);
        init_done = true;
    }

    // ---- fork ----
    cudaEventRecord(ev_fork, 0);
    cudaStreamWaitEvent(s1, ev_fork, 0);

    // Branch B (side stream): CSR build
    cudaMemsetAsync(counts_ptr, 0, (size_t)NN * sizeof(int), s1);
    detect_idx_kernel<<<1, 256, 0, s1>>>((const long long*)rows, E);
    hist_kernel<<<4096, 128, 0, s1>>>(rows, E);
    scan_blocksum_kernel<<<SCAN_NB, 256, 0, s1>>>();
    scan_top_kernel<<<1, 32, 0, s1>>>(E);
    scan_write_kernel<<<SCAN_NB, 256, 0, s1>>>();
    bucket_kernel<<<4096, 128, 0, s1>>>(rows, cols, vals, E);
    cudaEventRecord(ev_join, s1);

    // Branch A (capture stream): fp32->fp16 converts, then fp16 GEMM
    const long long a4 = (long long)M * DIN / 4;
    convert_a_kernel<<<2048, 256>>>((const float4*)features, (__half2*)ah, a4);
    convert_w_kernel<<<dim3(DOUT / 32, DIN / 32), dim3(32, 8)>>>(weight, bth);
    dim3 gemm_grid(DOUT / 128, (M + 127) / 128);
    gemm_fp16_kernel<<<gemm_grid, 256, H_SMEM_WORDS * 4>>>(ah, bth, sup, M);

    // ---- join ----
    cudaStreamWaitEvent(0, ev_join, 0);

    // Aggregation + fused ReLU
    aggregate_kernel<<<M, 128>>>(sup, out);
}

// round 8
// speedup vs baseline: 1.7050x; 1.5064x over previous
#include <cuda_runtime.h>
#include <cuda_fp16.h>
#include <cstdint>

// Problem constants (fixed by the reference)
#define NN    100000      // nodes
#define DIN   512
#define DOUT  512
#define EMAX  3200000     // edges

// Scratch (device globals per harness alloc rules)
__device__ __half g_suph[(size_t)NN * DOUT];       // 100 MB, support in fp16 (fits L2!)
__device__ __half g_Ah[(size_t)NN * DIN];          // 100 MB, A in fp16
__device__ __half g_Bth[DIN * DOUT];               // 0.5 MB, W^T in fp16 (n-major)
__device__ int    g_counts [NN];
__device__ int    g_offsets[NN + 1];
__device__ int    g_cursor [NN];
__device__ int    g_blocksums[128];
__device__ int    g_ecol[EMAX];
__device__ float  g_eval[EMAX];
__device__ int    g_idx_is64;

#define SCAN_ELEMS 1024
#define SCAN_NB   ((NN + SCAN_ELEMS - 1) / SCAN_ELEMS)   // 98

// ---------------------------------------------------------------------------
// Kernel: detect index dtype (int64 vs int32-packed).
// ---------------------------------------------------------------------------
__global__ void detect_idx_kernel(const long long* __restrict__ rows, int n_edges)
{
    __shared__ int bad;
    if (threadIdx.x == 0) bad = 0;
    __syncthreads();
    int limit = 2048;
    if (limit > n_edges / 2) limit = n_edges / 2;
    for (int i = threadIdx.x; i < limit; i += blockDim.x) {
        long long v = rows[i];
        if (v < 0 || v >= NN) bad = 1;
    }
    __syncthreads();
    if (threadIdx.x == 0) g_idx_is64 = bad ? 0 : 1;
}

__device__ __forceinline__ long long load_idx(const void* p, int e)
{
    if (g_idx_is64) return ((const long long*)p)[e];
    return (long long)((const int*)p)[e];
}

// ---------------------------------------------------------------------------
// Convert A fp32 -> fp16 (streaming, float4 in / half2 out).
// ---------------------------------------------------------------------------
__global__ __launch_bounds__(256)
void convert_a_kernel(const float4* __restrict__ in, __half2* __restrict__ out,
                      long long n4)
{
    long long i = (long long)blockIdx.x * blockDim.x + threadIdx.x;
    long long stride = (long long)gridDim.x * blockDim.x;
    for (; i < n4; i += stride) {
        float4 v = in[i];
        out[i * 2 + 0] = __floats2half2_rn(v.x, v.y);
        out[i * 2 + 1] = __floats2half2_rn(v.z, v.w);
    }
}

// ---------------------------------------------------------------------------
// Convert + transpose W: Bth[n][k] = (half)W[k][n].
// ---------------------------------------------------------------------------
__global__ void convert_w_kernel(const float* __restrict__ W, __half* __restrict__ Bth)
{
    __shared__ float tile[32][33];
    int bx = blockIdx.x * 32, by = blockIdx.y * 32;   // bx: n, by: k
    int tx = threadIdx.x, ty = threadIdx.y;           // 32 x 8
#pragma unroll
    for (int i = 0; i < 32; i += 8)
        tile[ty + i][tx] = W[(by + ty + i) * DOUT + bx + tx];
    __syncthreads();
#pragma unroll
    for (int i = 0; i < 32; i += 8)
        Bth[(long long)(bx + ty + i) * DIN + by + tx] = __float2half_rn(tile[tx][ty + i]);
}

// ---------------------------------------------------------------------------
// FP16 tensor-core GEMM, fp32 accum, fp16 OUTPUT (support).
// BM=BN=128, BK=64, 8 warps (2Mx4N). m16n8k16. cp.async double-buffered.
// ---------------------------------------------------------------------------
#define HS_STRIDE 36
#define H_BUF_WORDS (128 * HS_STRIDE)
#define H_SMEM_WORDS (4 * H_BUF_WORDS)

__device__ __forceinline__ void cp_async16(uint32_t saddr, const void* gptr, int src_bytes)
{
    asm volatile("cp.async.cg.shared.global [%0], [%1], 16, %2;\n"
                 :: "r"(saddr), "l"(gptr), "r"(src_bytes));
}

__global__ __launch_bounds__(256, 2)
void gemm_fp16_kernel(const __half* __restrict__ A, const __half* __restrict__ Bt,
                      __half* __restrict__ C, int M)
{
    extern __shared__ uint32_t smem[];
    const int tid  = threadIdx.x;
    const int wid  = tid >> 5;
    const int lane = tid & 31;
    const int gid  = lane >> 2;
    const int tg   = lane & 3;

    const int blockRow = blockIdx.y * 128;
    const int blockCol = blockIdx.x * 128;

    const int ldRow = tid >> 3;
    const int ldCol = (tid & 7) * 4;

    uint32_t smem_base;
    asm("{ .reg .u64 t; cvta.to.shared.u64 t, %1; cvt.u32.u64 %0, t; }"
        : "=r"(smem_base) : "l"(smem));

    const int warpM = (wid & 1) * 64;
    const int warpN = (wid >> 1) * 32;

    float acc[4][4][4];
#pragma unroll
    for (int i = 0; i < 4; i++)
#pragma unroll
        for (int j = 0; j < 4; j++)
#pragma unroll
            for (int t = 0; t < 4; t++) acc[i][j][t] = 0.f;

    auto issue_chunk = [&](int chunk, int buf) {
        const int kElem = chunk * 64 + ldCol * 2;
#pragma unroll
        for (int l = 0; l < 4; l++) {
            int r = ldRow + 32 * l;
            long long gRow = (long long)blockRow + r;
            bool ok = gRow < M;
            const __half* src = A + (ok ? gRow : 0) * DIN + kElem;
            uint32_t dst = smem_base + (buf * H_BUF_WORDS + r * HS_STRIDE + ldCol) * 4;
            cp_async16(dst, src, ok ? 16 : 0);
        }
#pragma unroll
        for (int l = 0; l < 4; l++) {
            int n = ldRow + 32 * l;
            const __half* src = Bt + (long long)(blockCol + n) * DIN + kElem;
            uint32_t dst = smem_base +
                ((2 + buf) * H_BUF_WORDS + n * HS_STRIDE + ldCol) * 4;
            cp_async16(dst, src, 16);
        }
        asm volatile("cp.async.commit_group;");
    };

    issue_chunk(0, 0);

    const int NCHUNK = DIN / 64;   // 8
    int buf = 0;
    for (int c = 0; c < NCHUNK; c++) {
        if (c + 1 < NCHUNK) {
            issue_chunk(c + 1, buf ^ 1);
            asm volatile("cp.async.wait_group 1;");
        } else {
            asm volatile("cp.async.wait_group 0;");
        }
        __syncthreads();

        const uint32_t* As = smem + buf * H_BUF_WORDS;
        const uint32_t* Bs = smem + (2 + buf) * H_BUF_WORDS;

#pragma unroll
        for (int s = 0; s < 4; s++) {
            const int kw = s * 8;
            uint32_t afr[4][4], bfr[4][2];
#pragma unroll
            for (int i = 0; i < 4; i++) {
                int r0 = warpM + i * 16 + gid;
                afr[i][0] = As[(r0)     * HS_STRIDE + kw + tg];
                afr[i][1] = As[(r0 + 8) * HS_STRIDE + kw + tg];
                afr[i][2] = As[(r0)     * HS_STRIDE + kw + 4 + tg];
                afr[i][3] = As[(r0 + 8) * HS_STRIDE + kw + 4 + tg];
            }
#pragma unroll
            for (int j = 0; j < 4; j++) {
                int nn = warpN + j * 8 + gid;
                bfr[j][0] = Bs[nn * HS_STRIDE + kw + tg];
                bfr[j][1] = Bs[nn * HS_STRIDE + kw + 4 + tg];
            }
#pragma unroll
            for (int i = 0; i < 4; i++)
#pragma unroll
                for (int j = 0; j < 4; j++) {
                    asm volatile(
                        "mma.sync.aligned.m16n8k16.row.col.f32.f16.f16.f32 "
                        "{%0,%1,%2,%3}, {%4,%5,%6,%7}, {%8,%9}, {%0,%1,%2,%3};"
                        : "+f"(acc[i][j][0]), "+f"(acc[i][j][1]),
                          "+f"(acc[i][j][2]), "+f"(acc[i][j][3])
                        : "r"(afr[i][0]), "r"(afr[i][1]), "r"(afr[i][2]), "r"(afr[i][3]),
                          "r"(bfr[j][0]), "r"(bfr[j][1]));
                }
        }
        __syncthreads();
        buf ^= 1;
    }

    // Epilogue: fp16 output (half2 per register pair)
#pragma unroll
    for (int i = 0; i < 4; i++) {
        long long row0 = (long long)blockRow + warpM + i * 16 + gid;
#pragma unroll
        for (int j = 0; j < 4; j++) {
            int col = blockCol + warpN + j * 8 + tg * 2;
            if (row0 < M)
                *(__half2*)(C + row0 * DOUT + col) =
                    __floats2half2_rn(acc[i][j][0], acc[i][j][1]);
            if (row0 + 8 < M)
                *(__half2*)(C + (row0 + 8) * DOUT + col) =
                    __floats2half2_rn(acc[i][j][2], acc[i][j][3]);
        }
    }
}

// ---------------------------------------------------------------------------
// CSR build (unchanged)
// ---------------------------------------------------------------------------
__global__ __launch_bounds__(128)
void hist_kernel(const void* __restrict__ rows, int E)
{
    int stride = gridDim.x * blockDim.x;
    for (int e = blockIdx.x * blockDim.x + threadIdx.x; e < E; e += stride) {
        int r = (int)load_idx(rows, e);
        atomicAdd(&g_counts[r], 1);
    }
}

__global__ __launch_bounds__(256)
void scan_blocksum_kernel()
{
    __shared__ int sh[256];
    int b = blockIdx.x, t = threadIdx.x;
    int base = b * SCAN_ELEMS + t * 4;
    int s = 0;
#pragma unroll
    for (int i = 0; i < 4; i++) {
        int idx = base + i;
        if (idx < NN) s += g_counts[idx];
    }
    sh[t] = s; __syncthreads();
    for (int off = 128; off > 0; off >>= 1) {
        if (t < off) sh[t] += sh[t + off];
        __syncthreads();
    }
    if (t == 0) g_blocksums[b] = sh[0];
}

__global__ void scan_top_kernel(int E)
{
    if (threadIdx.x == 0) {
        int run = 0;
        for (int i = 0; i < SCAN_NB; i++) {
            int v = g_blocksums[i];
            g_blocksums[i] = run;
            run += v;
        }
        g_offsets[NN] = E;
    }
}

__global__ __launch_bounds__(256)
void scan_write_kernel()
{
    __shared__ int sh[256];
    int b = blockIdx.x, t = threadIdx.x;
    int base = b * SCAN_ELEMS + t * 4;
    int v[4];
#pragma unroll
    for (int i = 0; i < 4; i++)
        v[i] = (base + i < NN) ? g_counts[base + i] : 0;
    int s = v[0] + v[1] + v[2] + v[3];
    sh[t] = s; __syncthreads();
    for (int off = 1; off < 256; off <<= 1) {
        int x = (t >= off) ? sh[t - off] : 0;
        __syncthreads();
        sh[t] += x;
        __syncthreads();
    }
    int excl = sh[t] - s + g_blocksums[b];
#pragma unroll
    for (int i = 0; i < 4; i++) {
        int idx = base + i;
        if (idx < NN) {
            g_offsets[idx] = excl;
            g_cursor[idx]  = excl;
        }
        excl += v[i];
    }
}

__global__ __launch_bounds__(128)
void bucket_kernel(const void* __restrict__ rows, const void* __restrict__ cols,
                   const float* __restrict__ vals, int E)
{
    int stride = gridDim.x * blockDim.x;
    for (int e = blockIdx.x * blockDim.x + threadIdx.x; e < E; e += stride) {
        int r = (int)load_idx(rows, e);
        int c = (int)load_idx(cols, e);
        int pos = atomicAdd(&g_cursor[r], 1);
        g_ecol[pos] = c;
        g_eval[pos] = vals[e];
    }
}

// ---------------------------------------------------------------------------
// Aggregation over fp16 support: one block (128 thr) per node. Each thread
// owns 4 output floats; gathers uint2 (4 halves = 8 B) per edge. fp32 accum,
// fused ReLU, single fp32 write.
// ---------------------------------------------------------------------------
__global__ __launch_bounds__(128)
void aggregate_kernel(const __half* __restrict__ sup, float* __restrict__ out)
{
    const int node = blockIdx.x;
    const int t = threadIdx.x;
    const int beg = g_offsets[node];
    const int end = g_offsets[node + 1];

    __shared__ int   sc[128];
    __shared__ float sv[128];

    float4 acc = make_float4(0.f, 0.f, 0.f, 0.f);

    for (int j0 = beg; j0 < end; j0 += 128) {
        int m = end - j0; if (m > 128) m = 128;
        if (t < m) { sc[t] = g_ecol[j0 + t]; sv[t] = g_eval[j0 + t]; }
        __syncthreads();

        int k = 0;
        for (; k + 4 <= m; k += 4) {
            const uint2* p0 = (const uint2*)(sup + (long long)sc[k + 0] * DOUT) + t;
            const uint2* p1 = (const uint2*)(sup + (long long)sc[k + 1] * DOUT) + t;
            const uint2* p2 = (const uint2*)(sup + (long long)sc[k + 2] * DOUT) + t;
            const uint2* p3 = (const uint2*)(sup + (long long)sc[k + 3] * DOUT) + t;
            uint2 u0 = __ldg(p0), u1 = __ldg(p1), u2 = __ldg(p2), u3 = __ldg(p3);
            float v0 = sv[k + 0], v1 = sv[k + 1], v2 = sv[k + 2], v3 = sv[k + 3];

            float2 a0 = __half22float2(*(__half2*)&u0.x), b0 = __half22float2(*(__half2*)&u0.y);
            float2 a1 = __half22float2(*(__half2*)&u1.x), b1 = __half22float2(*(__half2*)&u1.y);
            float2 a2 = __half22float2(*(__half2*)&u2.x), b2 = __half22float2(*(__half2*)&u2.y);
            float2 a3 = __half22float2(*(__half2*)&u3.x), b3 = __half22float2(*(__half2*)&u3.y);

            acc.x += v0 * a0.x; acc.y += v0 * a0.y; acc.z += v0 * b0.x; acc.w += v0 * b0.y;
            acc.x += v1 * a1.x; acc.y += v1 * a1.y; acc.z += v1 * b1.x; acc.w += v1 * b1.y;
            acc.x += v2 * a2.x; acc.y += v2 * a2.y; acc.z += v2 * b2.x; acc.w += v2 * b2.y;
            acc.x += v3 * a3.x; acc.y += v3 * a3.y; acc.z += v3 * b3.x; acc.w += v3 * b3.y;
        }
        for (; k < m; k++) {
            uint2 u = __ldg((const uint2*)(sup + (long long)sc[k] * DOUT) + t);
            float v = sv[k];
            float2 a = __half22float2(*(__half2*)&u.x), b = __half22float2(*(__half2*)&u.y);
            acc.x += v * a.x; acc.y += v * a.y; acc.z += v * b.x; acc.w += v * b.y;
        }
        __syncthreads();
    }

    acc.x = fmaxf(acc.x, 0.f); acc.y = fmaxf(acc.y, 0.f);
    acc.z = fmaxf(acc.z, 0.f); acc.w = fmaxf(acc.w, 0.f);
    ((float4*)out)[(long long)node * (DOUT / 4) + t] = acc;
}

// ---------------------------------------------------------------------------
// kernel_launch
// ---------------------------------------------------------------------------
extern "C" void kernel_launch(void* const* d_in, const int* in_sizes, int n_in,
                              void* d_out, int out_size)
{
    const float* features = (const float*)d_in[0];
    const float* weight   = (const float*)d_in[1];
    const void*  rows     = d_in[2];
    const void*  cols     = d_in[3];
    const float* vals     = (const float*)d_in[4];
    float* out = (float*)d_out;

    const int M = in_sizes[0] / DIN;   // 100000
    const int E = in_sizes[4];         // 3200000

    __half* suph = nullptr;
    cudaGetSymbolAddress((void**)&suph, g_suph);
    __half* ah = nullptr;
    cudaGetSymbolAddress((void**)&ah, g_Ah);
    __half* bth = nullptr;
    cudaGetSymbolAddress((void**)&bth, g_Bth);
    int* counts_ptr = nullptr;
    cudaGetSymbolAddress((void**)&counts_ptr, g_counts);

    static bool init_done = false;
    static cudaStream_t s1;
    static cudaEvent_t ev_fork, ev_join;
    if (!init_done) {
        cudaFuncSetAttribute(gemm_fp16_kernel,
                             cudaFuncAttributeMaxDynamicSharedMemorySize,
                             H_SMEM_WORDS * 4);
        cudaStreamCreateWithFlags(&s1, cudaStreamNonBlocking);
        cudaEventCreateWithFlags(&ev_fork, cudaEventDisableTiming);
        cudaEventCreateWithFlags(&ev_join, cudaEventDisableTiming);
        init_done = true;
    }

    // ---- fork ----
    cudaEventRecord(ev_fork, 0);
    cudaStreamWaitEvent(s1, ev_fork, 0);

    // Branch B (side stream): CSR build
    cudaMemsetAsync(counts_ptr, 0, (size_t)NN * sizeof(int), s1);
    detect_idx_kernel<<<1, 256, 0, s1>>>((const long long*)rows, E);
    hist_kernel<<<4096, 128, 0, s1>>>(rows, E);
    scan_blocksum_kernel<<<SCAN_NB, 256, 0, s1>>>();
    scan_top_kernel<<<1, 32, 0, s1>>>(E);
    scan_write_kernel<<<SCAN_NB, 256, 0, s1>>>();
    bucket_kernel<<<4096, 128, 0, s1>>>(rows, cols, vals, E);
    cudaEventRecord(ev_join, s1);

    // Branch A (capture stream): fp32->fp16 converts, then fp16 GEMM
    const long long a4 = (long long)M * DIN / 4;
    convert_a_kernel<<<2048, 256>>>((const float4*)features, (__half2*)ah, a4);
    convert_w_kernel<<<dim3(DOUT / 32, DIN / 32), dim3(32, 8)>>>(weight, bth);
    dim3 gemm_grid(DOUT / 128, (M + 127) / 128);
    gemm_fp16_kernel<<<gemm_grid, 256, H_SMEM_WORDS * 4>>>(ah, bth, suph, M);

    // ---- join ----
    cudaStreamWaitEvent(0, ev_join, 0);

    // Aggregation over fp16 support + fused ReLU
    aggregate_kernel<<<M, 128>>>(suph, out);
}

// round 9
// speedup vs baseline: 1.7577x; 1.0309x over previous
#include <cuda_runtime.h>
#include <cuda_fp16.h>
#include <cstdint>

// Problem constants (fixed by the reference)
#define NN    100000      // nodes
#define DIN   512
#define DOUT  512
#define EMAX  3200000     // edges

// Scratch (device globals per harness alloc rules)
__device__ __half g_suph[(size_t)NN * DOUT];       // 100 MB, support in fp16 (fits L2)
__device__ __half g_Ah[(size_t)NN * DIN];          // 100 MB, A in fp16
__device__ __half g_Bth[DIN * DOUT];               // 0.5 MB, W^T in fp16 (n-major)
__device__ int    g_counts [NN];
__device__ int    g_offsets[NN + 1];
__device__ int    g_cursor [NN];
__device__ int    g_blocksums[128];
__device__ int    g_ecol[EMAX];
__device__ float  g_eval[EMAX];
__device__ int    g_idx_is64;

#define SCAN_ELEMS 1024
#define SCAN_NB   ((NN + SCAN_ELEMS - 1) / SCAN_ELEMS)   // 98

// ---------------------------------------------------------------------------
// Kernel: detect index dtype (int64 vs int32-packed).
// ---------------------------------------------------------------------------
__global__ void detect_idx_kernel(const long long* __restrict__ rows, int n_edges)
{
    __shared__ int bad;
    if (threadIdx.x == 0) bad = 0;
    __syncthreads();
    int limit = 2048;
    if (limit > n_edges / 2) limit = n_edges / 2;
    for (int i = threadIdx.x; i < limit; i += blockDim.x) {
        long long v = rows[i];
        if (v < 0 || v >= NN) bad = 1;
    }
    __syncthreads();
    if (threadIdx.x == 0) g_idx_is64 = bad ? 0 : 1;
}

__device__ __forceinline__ long long load_idx(const void* p, int e)
{
    if (g_idx_is64) return ((const long long*)p)[e];
    return (long long)((const int*)p)[e];
}

// ---------------------------------------------------------------------------
// Convert A fp32 -> fp16 (streaming, float4 in / half2 out).
// ---------------------------------------------------------------------------
__global__ __launch_bounds__(256)
void convert_a_kernel(const float4* __restrict__ in, __half2* __restrict__ out,
                      long long n4)
{
    long long i = (long long)blockIdx.x * blockDim.x + threadIdx.x;
    long long stride = (long long)gridDim.x * blockDim.x;
    for (; i < n4; i += stride) {
        float4 v = in[i];
        out[i * 2 + 0] = __floats2half2_rn(v.x, v.y);
        out[i * 2 + 1] = __floats2half2_rn(v.z, v.w);
    }
}

// ---------------------------------------------------------------------------
// Convert + transpose W: Bth[n][k] = (half)W[k][n].
// ---------------------------------------------------------------------------
__global__ void convert_w_kernel(const float* __restrict__ W, __half* __restrict__ Bth)
{
    __shared__ float tile[32][33];
    int bx = blockIdx.x * 32, by = blockIdx.y * 32;   // bx: n, by: k
    int tx = threadIdx.x, ty = threadIdx.y;           // 32 x 8
#pragma unroll
    for (int i = 0; i < 32; i += 8)
        tile[ty + i][tx] = W[(by + ty + i) * DOUT + bx + tx];
    __syncthreads();
#pragma unroll
    for (int i = 0; i < 32; i += 8)
        Bth[(long long)(bx + ty + i) * DIN + by + tx] = __float2half_rn(tile[tx][ty + i]);
}

// ---------------------------------------------------------------------------
// FP16 tensor-core GEMM, fp32 accum, fp16 OUTPUT (support).
// BM=BN=128, BK=64, 8 warps (2Mx4N). m16n8k16.
// R9: fragment loads via ldmatrix.m8n8.x4 (24 LDSM/chunk vs 96 scalar LDS).
// ---------------------------------------------------------------------------
#define HS_STRIDE 36
#define H_BUF_WORDS (128 * HS_STRIDE)
#define H_SMEM_WORDS (4 * H_BUF_WORDS)

__device__ __forceinline__ void cp_async16(uint32_t saddr, const void* gptr, int src_bytes)
{
    asm volatile("cp.async.cg.shared.global [%0], [%1], 16, %2;\n"
                 :: "r"(saddr), "l"(gptr), "r"(src_bytes));
}

__device__ __forceinline__ void ldsm_x4(uint32_t& r0, uint32_t& r1,
                                        uint32_t& r2, uint32_t& r3, uint32_t addr)
{
    asm volatile("ldmatrix.sync.aligned.m8n8.x4.shared.b16 {%0,%1,%2,%3}, [%4];"
                 : "=r"(r0), "=r"(r1), "=r"(r2), "=r"(r3) : "r"(addr));
}

__global__ __launch_bounds__(256, 2)
void gemm_fp16_kernel(const __half* __restrict__ A, const __half* __restrict__ Bt,
                      __half* __restrict__ C, int M)
{
    extern __shared__ uint32_t smem[];
    const int tid  = threadIdx.x;
    const int wid  = tid >> 5;
    const int lane = tid & 31;
    const int gid  = lane >> 2;
    const int tg   = lane & 3;

    const int blockRow = blockIdx.y * 128;
    const int blockCol = blockIdx.x * 128;

    const int ldRow = tid >> 3;
    const int ldCol = (tid & 7) * 4;

    uint32_t smem_base;
    asm("{ .reg .u64 t; cvta.to.shared.u64 t, %1; cvt.u32.u64 %0, t; }"
        : "=r"(smem_base) : "l"(smem));

    const int warpM = (wid & 1) * 64;
    const int warpN = (wid >> 1) * 32;

    // ldmatrix lane geometry: block lb = lane/8, row-in-block lr = lane%8
    const int lb = lane >> 3;
    const int lr = lane & 7;
    // A x4: blocks = (rows+0,kw),(rows+8,kw),(rows+0,kw+4),(rows+8,kw+4)
    const int a_lane_off = ((lb & 1) * 8 + lr) * HS_STRIDE + (lb >> 1) * 4;   // words
    // B x4: blocks = (j0,kw),(j0,kw+4),(j1,kw),(j1,kw+4); j = j0 + (lb>>1)
    const int b_lane_row = (lb >> 1) * 8 + lr;       // n offset within j-pair group
    const int b_lane_w   = (lb & 1) * 4;             // word offset

    float acc[4][4][4];
#pragma unroll
    for (int i = 0; i < 4; i++)
#pragma unroll
        for (int j = 0; j < 4; j++)
#pragma unroll
            for (int t = 0; t < 4; t++) acc[i][j][t] = 0.f;

    auto issue_chunk = [&](int chunk, int buf) {
        const int kElem = chunk * 64 + ldCol * 2;
#pragma unroll
        for (int l = 0; l < 4; l++) {
            int r = ldRow + 32 * l;
            long long gRow = (long long)blockRow + r;
            bool ok = gRow < M;
            const __half* src = A + (ok ? gRow : 0) * DIN + kElem;
            uint32_t dst = smem_base + (buf * H_BUF_WORDS + r * HS_STRIDE + ldCol) * 4;
            cp_async16(dst, src, ok ? 16 : 0);
        }
#pragma unroll
        for (int l = 0; l < 4; l++) {
            int n = ldRow + 32 * l;
            const __half* src = Bt + (long long)(blockCol + n) * DIN + kElem;
            uint32_t dst = smem_base +
                ((2 + buf) * H_BUF_WORDS + n * HS_STRIDE + ldCol) * 4;
            cp_async16(dst, src, 16);
        }
        asm volatile("cp.async.commit_group;");
    };

    issue_chunk(0, 0);

    const int NCHUNK = DIN / 64;   // 8
    int buf = 0;
    for (int c = 0; c < NCHUNK; c++) {
        if (c + 1 < NCHUNK) {
            issue_chunk(c + 1, buf ^ 1);
            asm volatile("cp.async.wait_group 1;");
        } else {
            asm volatile("cp.async.wait_group 0;");
        }
        __syncthreads();

        const uint32_t aBase = smem_base + (buf * H_BUF_WORDS) * 4;
        const uint32_t bBase = smem_base + ((2 + buf) * H_BUF_WORDS) * 4;

#pragma unroll
        for (int s = 0; s < 4; s++) {
            const int kw = s * 8;
            uint32_t afr[4][4], bfr[4][2];
#pragma unroll
            for (int i = 0; i < 4; i++) {
                uint32_t addr = aBase +
                    ((warpM + i * 16) * HS_STRIDE + kw + a_lane_off) * 4;
                ldsm_x4(afr[i][0], afr[i][1], afr[i][2], afr[i][3], addr);
            }
#pragma unroll
            for (int jj = 0; jj < 2; jj++) {
                const int j0 = jj * 2;
                uint32_t addr = bBase +
                    ((warpN + j0 * 8 + b_lane_row) * HS_STRIDE + kw + b_lane_w) * 4;
                ldsm_x4(bfr[j0][0], bfr[j0][1], bfr[j0 + 1][0], bfr[j0 + 1][1], addr);
            }
#pragma unroll
            for (int i = 0; i < 4; i++)
#pragma unroll
                for (int j = 0; j < 4; j++) {
                    asm volatile(
                        "mma.sync.aligned.m16n8k16.row.col.f32.f16.f16.f32 "
                        "{%0,%1,%2,%3}, {%4,%5,%6,%7}, {%8,%9}, {%0,%1,%2,%3};"
                        : "+f"(acc[i][j][0]), "+f"(acc[i][j][1]),
                          "+f"(acc[i][j][2]), "+f"(acc[i][j][3])
                        : "r"(afr[i][0]), "r"(afr[i][1]), "r"(afr[i][2]), "r"(afr[i][3]),
                          "r"(bfr[j][0]), "r"(bfr[j][1]));
                }
        }
        __syncthreads();
        buf ^= 1;
    }

    // Epilogue: fp16 output (half2 per register pair)
#pragma unroll
    for (int i = 0; i < 4; i++) {
        long long row0 = (long long)blockRow + warpM + i * 16 + gid;
#pragma unroll
        for (int j = 0; j < 4; j++) {
            int col = blockCol + warpN + j * 8 + tg * 2;
            if (row0 < M)
                *(__half2*)(C + row0 * DOUT + col) =
                    __floats2half2_rn(acc[i][j][0], acc[i][j][1]);
            if (row0 + 8 < M)
                *(__half2*)(C + (row0 + 8) * DOUT + col) =
                    __floats2half2_rn(acc[i][j][2], acc[i][j][3]);
        }
    }
}

// ---------------------------------------------------------------------------
// CSR build (unchanged)
// ---------------------------------------------------------------------------
__global__ __launch_bounds__(128)
void hist_kernel(const void* __restrict__ rows, int E)
{
    int stride = gridDim.x * blockDim.x;
    for (int e = blockIdx.x * blockDim.x + threadIdx.x; e < E; e += stride) {
        int r = (int)load_idx(rows, e);
        atomicAdd(&g_counts[r], 1);
    }
}

__global__ __launch_bounds__(256)
void scan_blocksum_kernel()
{
    __shared__ int sh[256];
    int b = blockIdx.x, t = threadIdx.x;
    int base = b * SCAN_ELEMS + t * 4;
    int s = 0;
#pragma unroll
    for (int i = 0; i < 4; i++) {
        int idx = base + i;
        if (idx < NN) s += g_counts[idx];
    }
    sh[t] = s; __syncthreads();
    for (int off = 128; off > 0; off >>= 1) {
        if (t < off) sh[t] += sh[t + off];
        __syncthreads();
    }
    if (t == 0) g_blocksums[b] = sh[0];
}

__global__ void scan_top_kernel(int E)
{
    if (threadIdx.x == 0) {
        int run = 0;
        for (int i = 0; i < SCAN_NB; i++) {
            int v = g_blocksums[i];
            g_blocksums[i] = run;
            run += v;
        }
        g_offsets[NN] = E;
    }
}

__global__ __launch_bounds__(256)
void scan_write_kernel()
{
    __shared__ int sh[256];
    int b = blockIdx.x, t = threadIdx.x;
    int base = b * SCAN_ELEMS + t * 4;
    int v[4];
#pragma unroll
    for (int i = 0; i < 4; i++)
        v[i] = (base + i < NN) ? g_counts[base + i] : 0;
    int s = v[0] + v[1] + v[2] + v[3];
    sh[t] = s; __syncthreads();
    for (int off = 1; off < 256; off <<= 1) {
        int x = (t >= off) ? sh[t - off] : 0;
        __syncthreads();
        sh[t] += x;
        __syncthreads();
    }
    int excl = sh[t] - s + g_blocksums[b];
#pragma unroll
    for (int i = 0; i < 4; i++) {
        int idx = base + i;
        if (idx < NN) {
            g_offsets[idx] = excl;
            g_cursor[idx]  = excl;
        }
        excl += v[i];
    }
}

__global__ __launch_bounds__(128)
void bucket_kernel(const void* __restrict__ rows, const void* __restrict__ cols,
                   const float* __restrict__ vals, int E)
{
    int stride = gridDim.x * blockDim.x;
    for (int e = blockIdx.x * blockDim.x + threadIdx.x; e < E; e += stride) {
        int r = (int)load_idx(rows, e);
        int c = (int)load_idx(cols, e);
        int pos = atomicAdd(&g_cursor[r], 1);
        g_ecol[pos] = c;
        g_eval[pos] = vals[e];
    }
}

// ---------------------------------------------------------------------------
// Aggregation over fp16 support (unchanged R8): block per node, fp32 accum,
// fused ReLU.
// ---------------------------------------------------------------------------
__global__ __launch_bounds__(128)
void aggregate_kernel(const __half* __restrict__ sup, float* __restrict__ out)
{
    const int node = blockIdx.x;
    const int t = threadIdx.x;
    const int beg = g_offsets[node];
    const int end = g_offsets[node + 1];

    __shared__ int   sc[128];
    __shared__ float sv[128];

    float4 acc = make_float4(0.f, 0.f, 0.f, 0.f);

    for (int j0 = beg; j0 < end; j0 += 128) {
        int m = end - j0; if (m > 128) m = 128;
        if (t < m) { sc[t] = g_ecol[j0 + t]; sv[t] = g_eval[j0 + t]; }
        __syncthreads();

        int k = 0;
        for (; k + 4 <= m; k += 4) {
            const uint2* p0 = (const uint2*)(sup + (long long)sc[k + 0] * DOUT) + t;
            const uint2* p1 = (const uint2*)(sup + (long long)sc[k + 1] * DOUT) + t;
            const uint2* p2 = (const uint2*)(sup + (long long)sc[k + 2] * DOUT) + t;
            const uint2* p3 = (const uint2*)(sup + (long long)sc[k + 3] * DOUT) + t;
            uint2 u0 = __ldg(p0), u1 = __ldg(p1), u2 = __ldg(p2), u3 = __ldg(p3);
            float v0 = sv[k + 0], v1 = sv[k + 1], v2 = sv[k + 2], v3 = sv[k + 3];

            float2 a0 = __half22float2(*(__half2*)&u0.x), b0 = __half22float2(*(__half2*)&u0.y);
            float2 a1 = __half22float2(*(__half2*)&u1.x), b1 = __half22float2(*(__half2*)&u1.y);
            float2 a2 = __half22float2(*(__half2*)&u2.x), b2 = __half22float2(*(__half2*)&u2.y);
            float2 a3 = __half22float2(*(__half2*)&u3.x), b3 = __half22float2(*(__half2*)&u3.y);

            acc.x += v0 * a0.x; acc.y += v0 * a0.y; acc.z += v0 * b0.x; acc.w += v0 * b0.y;
            acc.x += v1 * a1.x; acc.y += v1 * a1.y; acc.z += v1 * b1.x; acc.w += v1 * b1.y;
            acc.x += v2 * a2.x; acc.y += v2 * a2.y; acc.z += v2 * b2.x; acc.w += v2 * b2.y;
            acc.x += v3 * a3.x; acc.y += v3 * a3.y; acc.z += v3 * b3.x; acc.w += v3 * b3.y;
        }
        for (; k < m; k++) {
            uint2 u = __ldg((const uint2*)(sup + (long long)sc[k] * DOUT) + t);
            float v = sv[k];
            float2 a = __half22float2(*(__half2*)&u.x), b = __half22float2(*(__half2*)&u.y);
            acc.x += v * a.x; acc.y += v * a.y; acc.z += v * b.x; acc.w += v * b.y;
        }
        __syncthreads();
    }

    acc.x = fmaxf(acc.x, 0.f); acc.y = fmaxf(acc.y, 0.f);
    acc.z = fmaxf(acc.z, 0.f); acc.w = fmaxf(acc.w, 0.f);
    ((float4*)out)[(long long)node * (DOUT / 4) + t] = acc;
}

// ---------------------------------------------------------------------------
// kernel_launch
// ---------------------------------------------------------------------------
extern "C" void kernel_launch(void* const* d_in, const int* in_sizes, int n_in,
                              void* d_out, int out_size)
{
    const float* features = (const float*)d_in[0];
    const float* weight   = (const float*)d_in[1];
    const void*  rows     = d_in[2];
    const void*  cols     = d_in[3];
    const float* vals     = (const float*)d_in[4];
    float* out = (float*)d_out;

    const int M = in_sizes[0] / DIN;   // 100000
    const int E = in_sizes[4];         // 3200000

    __half* suph = nullptr;
    cudaGetSymbolAddress((void**)&suph, g_suph);
    __half* ah = nullptr;
    cudaGetSymbolAddress((void**)&ah, g_Ah);
    __half* bth = nullptr;
    cudaGetSymbolAddress((void**)&bth, g_Bth);
    int* counts_ptr = nullptr;
    cudaGetSymbolAddress((void**)&counts_ptr, g_counts);

    static bool init_done = false;
    static cudaStream_t s1;
    static cudaEvent_t ev_fork, ev_join;
    if (!init_done) {
        cudaFuncSetAttribute(gemm_fp16_kernel,
                             cudaFuncAttributeMaxDynamicSharedMemorySize,
                             H_SMEM_WORDS * 4);
        cudaStreamCreateWithFlags(&s1, cudaStreamNonBlocking);
        cudaEventCreateWithFlags(&ev_fork, cudaEventDisableTiming);
        cudaEventCreateWithFlags(&ev_join, cudaEventDisableTiming);
        init_done = true;
    }

    // ---- fork ----
    cudaEventRecord(ev_fork, 0);
    cudaStreamWaitEvent(s1, ev_fork, 0);

    // Branch B (side stream): CSR build
    cudaMemsetAsync(counts_ptr, 0, (size_t)NN * sizeof(int), s1);
    detect_idx_kernel<<<1, 256, 0, s1>>>((const long long*)rows, E);
    hist_kernel<<<4096, 128, 0, s1>>>(rows, E);
    scan_blocksum_kernel<<<SCAN_NB, 256, 0, s1>>>();
    scan_top_kernel<<<1, 32, 0, s1>>>(E);
    scan_write_kernel<<<SCAN_NB, 256, 0, s1>>>();
    bucket_kernel<<<4096, 128, 0, s1>>>(rows, cols, vals, E);
    cudaEventRecord(ev_join, s1);

    // Branch A (capture stream): fp32->fp16 converts, then fp16 GEMM
    const long long a4 = (long long)M * DIN / 4;
    convert_a_kernel<<<2048, 256>>>((const float4*)features, (__half2*)ah, a4);
    convert_w_kernel<<<dim3(DOUT / 32, DIN / 32), dim3(32, 8)>>>(weight, bth);
    dim3 gemm_grid(DOUT / 128, (M + 127) / 128);
    gemm_fp16_kernel<<<gemm_grid, 256, H_SMEM_WORDS * 4>>>(ah, bth, suph, M);

    // ---- join ----
    cudaStreamWaitEvent(0, ev_join, 0);

    // Aggregation over fp16 support + fused ReLU
    aggregate_kernel<<<M, 128>>>(suph, out);
}